// round 6
// baseline (speedup 1.0000x reference)
#include <cuda_runtime.h>
#include <cstdint>

// PANNAcceptor: out[b] = lin_w @ (W[x_{L-1}] ... W[x_0] e0) + lin_b
// Round 6: fp24 weight compression (top 3 bytes of RN-rounded fp32).
//   - 25% less W traffic per step (192KB vs 256KB) -> higher chip step
//     throughput AND faster per-batch solo rate (the straggler bound).
//   - decode = 1 PRMT (+AND for straddling elements); no scales, no cvt.
//   - precision: rel err 2^-16/sqrt(3) per element -> ~3e-4 accumulated
//     over 1024 steps, well under the 1e-3 gate.
// Structure otherwise = R1 (best so far): 1 CTA/batch, 1 CTA/SM, h in smem.

#define NST  256
#define TPB  512          // 16 warps, 16 rows each
#define MAXA 128          // scratch sized for up to 128 symbols

// fp24 scratch: A * 256*256 elements * 3 bytes  (<= 25.2 MB for MAXA=128)
__device__ unsigned char g_w24[(size_t)MAXA * NST * NST * 3];

// ---------------- quantize: fp32 -> fp24 (RN via +0x80, keep top 24 bits) ---
__global__ void pann_quant(const float* __restrict__ W, int total4)
{
    // each iteration handles 4 consecutive floats -> 12 bytes (3 words)
    for (int i = blockIdx.x * blockDim.x + threadIdx.x; i < total4;
         i += gridDim.x * blockDim.x) {
        const float4 f = ((const float4*)W)[i];
        uint32_t v0 = (__float_as_uint(f.x) + 0x80u) >> 8;   // 24-bit payloads
        uint32_t v1 = (__float_as_uint(f.y) + 0x80u) >> 8;
        uint32_t v2 = (__float_as_uint(f.z) + 0x80u) >> 8;
        uint32_t v3 = (__float_as_uint(f.w) + 0x80u) >> 8;
        uint32_t* out = (uint32_t*)(g_w24 + (size_t)i * 12);
        out[0] = v0 | (v1 << 24);
        out[1] = (v1 >> 8) | (v2 << 16);
        out[2] = (v2 >> 16) | (v3 << 8);
    }
}

// decode helpers: rebuild fp32 = [00, b0, b1, b2] from the 3-byte stream
__device__ __forceinline__ float dec_a(uint32_t w, uint32_t sel) {
    return __uint_as_float(__byte_perm(w, 0u, sel));
}
__device__ __forceinline__ float dec_s(uint32_t lo, uint32_t hi, uint32_t sel) {
    return __uint_as_float(__byte_perm(lo, hi, sel) & 0xFFFFFF00u);
}

__device__ __forceinline__ float warp_reduce16(float v) {
    v += __shfl_xor_sync(0xffffffffu, v, 8);
    v += __shfl_xor_sync(0xffffffffu, v, 4);
    v += __shfl_xor_sync(0xffffffffu, v, 2);
    v += __shfl_xor_sync(0xffffffffu, v, 1);
    return v;
}

// dot of 8 fp24 cols (24 bytes at p) against 8 h values
__device__ __forceinline__ float row_dot24(const uint2* p, const float4 h0, const float4 h1)
{
    const uint2 u01 = p[0], u23 = p[1], u45 = p[2];
    const uint32_t w0 = u01.x, w1 = u01.y, w2 = u23.x,
                   w3 = u23.y, w4 = u45.x, w5 = u45.y;
    // elements k at bytes [3k, 3k+3) of the 24-byte stream
    const float e0 = dec_a(w0, 0x2104u);          // b0,b1,b2
    const float e1 = dec_s(w0, w1, 0x5430u);      // b3 | b4,b5
    const float e2 = dec_s(w1, w2, 0x4320u);      // b6,b7 | b8
    const float e3 = dec_a(w2, 0x3214u);          // b9,b10,b11
    const float e4 = dec_a(w3, 0x2104u);
    const float e5 = dec_s(w3, w4, 0x5430u);
    const float e6 = dec_s(w4, w5, 0x4320u);
    const float e7 = dec_a(w5, 0x3214u);
    return e0*h0.x + e1*h0.y + e2*h0.z + e3*h0.w
         + e4*h1.x + e5*h1.y + e6*h1.z + e7*h1.w;
}

// ---------------- main chain kernel (fp24 W) ----------------
__global__ __launch_bounds__(TPB, 1)
void pann_chain24(const int* __restrict__ xs,
                  const int* __restrict__ lengths,
                  const float* __restrict__ lin_w,
                  const float* __restrict__ lin_b,
                  float* __restrict__ out,
                  int S)
{
    __shared__ float hbuf[2][NST];

    const int b    = blockIdx.x;
    const int tid  = threadIdx.x;
    const int warp = tid >> 5;
    const int lane = tid & 31;

    if (tid < NST) hbuf[0][tid] = (tid == 0) ? 1.0f : 0.0f;

    const int L = lengths[b];
    const int* xrow = xs + (size_t)b * S;
    __syncthreads();

    int cur = 0;
    const int i0 = warp * 16;                 // this warp's 16 rows
    const int loff = lane * 24;               // lane's byte offset within a row
    int a = __ldg(xrow);

    for (int t = 0; t < L; ++t) {
        const int a_cur = a;
        if (t + 1 < L) a = __ldg(xrow + t + 1);     // prefetch next symbol

        const unsigned char* Wq =
            g_w24 + (size_t)a_cur * (NST * NST * 3);
        const float* hsrc = hbuf[cur];
        float* hdst = hbuf[cur ^ 1];

        // lane's h slice: cols [8l, 8l+8)
        const float4 h0 = ((const float4*)hsrc)[2 * lane];
        const float4 h1 = ((const float4*)hsrc)[2 * lane + 1];

        const unsigned char* base = Wq + (size_t)i0 * (NST * 3) + loff;

        #pragma unroll 4
        for (int j = 0; j < 16; j += 2) {
            const uint2* p0 = (const uint2*)(base + (size_t)j * (NST * 3));
            const uint2* p1 = (const uint2*)(base + (size_t)(j + 1) * (NST * 3));
            float sA = row_dot24(p0, h0, h1);
            float sB = row_dot24(p1, h0, h1);

            // fold: lanes<16 reduce row j, lanes>=16 reduce row j+1
            const float oA = __shfl_xor_sync(0xffffffffu, sA, 16);
            const float oB = __shfl_xor_sync(0xffffffffu, sB, 16);
            float v = (lane < 16) ? (sA + oA) : (sB + oB);
            v = warp_reduce16(v);
            if (lane == 0)  hdst[i0 + j]     = v;
            if (lane == 16) hdst[i0 + j + 1] = v;
        }
        __syncthreads();
        cur ^= 1;
    }

    // linear head
    const float* hf = hbuf[L & 1];
    if (warp < 2) {
        float s = 0.0f;
        #pragma unroll
        for (int i = lane; i < NST; i += 32)
            s += lin_w[warp * NST + i] * hf[i];
        s += __shfl_xor_sync(0xffffffffu, s, 16);
        s = warp_reduce16(s);
        if (lane == 0) out[b * 2 + warp] = s + lin_b[warp];
    }
}

// ---------------- fallback (R1, full fp32) for unexpected shapes ------------
__global__ __launch_bounds__(512, 1)
void pann_chain_fp32(const int* __restrict__ xs,
                     const int* __restrict__ lengths,
                     const float* __restrict__ W,
                     const float* __restrict__ lin_w,
                     const float* __restrict__ lin_b,
                     float* __restrict__ out,
                     int S)
{
    __shared__ float hbuf[2][NST];
    const int b = blockIdx.x, tid = threadIdx.x, warp = tid >> 5, lane = tid & 31;
    if (tid < NST) hbuf[0][tid] = (tid == 0) ? 1.0f : 0.0f;
    const int L = lengths[b];
    const int* xrow = xs + (size_t)b * S;
    __syncthreads();
    int cur = 0;
    const int i0 = warp * 16;
    for (int t = 0; t < L; ++t) {
        const int a = __ldg(xrow + t);
        const float* Wa = W + (size_t)a * (NST * NST);
        const float* hsrc = hbuf[cur];
        float* hdst = hbuf[cur ^ 1];
        const float4 hA = ((const float4*)hsrc)[lane];
        const float4 hB = ((const float4*)hsrc)[32 + lane];
        #pragma unroll 4
        for (int r = 0; r < 16; ++r) {
            const int i = i0 + r;
            const float4* p = (const float4*)(Wa + (size_t)i * NST + lane * 4);
            const float4 wA = p[0];
            const float4 wB = p[32];
            float s = wA.x*hA.x + wA.y*hA.y + wA.z*hA.z + wA.w*hA.w
                    + wB.x*hB.x + wB.y*hB.y + wB.z*hB.z + wB.w*hB.w;
            s += __shfl_xor_sync(0xffffffffu, s, 16);
            s = warp_reduce16(s);
            if (lane == 0) hdst[i] = s;
        }
        __syncthreads();
        cur ^= 1;
    }
    const float* hf = hbuf[cur];
    if (warp < 2) {
        float s = 0.0f;
        #pragma unroll
        for (int i = lane; i < NST; i += 32) s += lin_w[warp * NST + i] * hf[i];
        s += __shfl_xor_sync(0xffffffffu, s, 16);
        s = warp_reduce16(s);
        if (lane == 0) out[b * 2 + warp] = s + lin_b[warp];
    }
}

extern "C" void kernel_launch(void* const* d_in, const int* in_sizes, int n_in,
                              void* d_out, int out_size)
{
    const int*   xs      = (const int*)d_in[0];
    const int*   lengths = (const int*)d_in[1];
    const float* W       = (const float*)d_in[2];
    const float* lin_w   = (const float*)d_in[3];
    const float* lin_b   = (const float*)d_in[4];
    float*       out     = (float*)d_out;

    const int B = in_sizes[1];
    const int S = in_sizes[0] / B;
    const int A = in_sizes[2] / (NST * NST);

    if (A >= 1 && A <= MAXA) {
        const int total4 = in_sizes[2] / 4;          // float4 count
        pann_quant<<<4096, 256>>>(W, total4);
        pann_chain24<<<B, TPB>>>(xs, lengths, lin_w, lin_b, out, S);
    } else {
        pann_chain_fp32<<<B, 512>>>(xs, lengths, W, lin_w, lin_b, out, S);
    }
}